// round 14
// baseline (speedup 1.0000x reference)
#include <cuda_runtime.h>
#include <cuda_bf16.h>
#include <cstdint>

#define NPTS 1024
#define DIM  256

// ---------------------------------------------------------------------------
// Scratch (__device__ globals). All PRE-SWIZZLED 8KB tile-chunks:
// block = 128 rows x 32 cols(bf16), row r / quad q at offset swz(r,q).
// ---------------------------------------------------------------------------
__device__ __align__(16) __nv_bfloat16 g_Xhi[16384 * 256];
__device__ __align__(16) __nv_bfloat16 g_Xlo[16384 * 256];
__device__ __align__(16) __nv_bfloat16 g_Wthi[2 * 256 * 256];
__device__ __align__(16) __nv_bfloat16 g_Wtlo[2 * 256 * 256];
__device__ __align__(16) __nv_bfloat16 g_Yhi[2 * 16384 * 256];
__device__ __align__(16) __nv_bfloat16 g_Ylo[2 * 16384 * 256];

#define TILE_BYTES 8192
#define BLOCK_BYTES 65536
#define BUF_BYTES  (4 * TILE_BYTES)   // Ah, Al, Bh, Bl = 32768
#define SMEM_TOTAL (3 * BUF_BYTES)    // 98304; x2 CTAs = 192K <= 228K/SM

__device__ __forceinline__ uint32_t smem_u32(const void* p) {
    uint32_t a;
    asm("{ .reg .u64 t; cvta.to.shared.u64 t, %1; cvt.u32.u64 %0, t; }" : "=r"(a) : "l"(p));
    return a;
}
__device__ __forceinline__ uint32_t bfu(__nv_bfloat16 v) {
    return (uint32_t)__bfloat16_as_ushort(v);
}
__device__ __forceinline__ uint32_t swz(int r, int q) {
    return (uint32_t)(r * 64 + (((q + (r >> 1)) & 3) << 4));
}

__device__ __forceinline__ void mma16816(float* d, const uint32_t* a, const uint32_t* b) {
    asm volatile(
        "mma.sync.aligned.m16n8k16.row.col.f32.bf16.bf16.f32 "
        "{%0,%1,%2,%3}, {%4,%5,%6,%7}, {%8,%9}, {%0,%1,%2,%3};\n"
        : "+f"(d[0]), "+f"(d[1]), "+f"(d[2]), "+f"(d[3])
        : "r"(a[0]), "r"(a[1]), "r"(a[2]), "r"(a[3]), "r"(b[0]), "r"(b[1]));
}
#define LDSM4(r0, r1, r2, r3, addr) \
    asm volatile("ldmatrix.sync.aligned.m8n8.x4.shared.b16 {%0,%1,%2,%3}, [%4];" \
        : "=r"(r0), "=r"(r1), "=r"(r2), "=r"(r3) : "r"(addr))

#define MBAR_INIT(a, c) \
    asm volatile("mbarrier.init.shared.b64 [%0], %1;" :: "r"(a), "r"(c) : "memory")
#define MBAR_EXPECT(a, n) \
    asm volatile("mbarrier.arrive.expect_tx.shared.b64 _, [%0], %1;" :: "r"(a), "r"(n) : "memory")
#define MBAR_ARRIVE(a) \
    asm volatile("mbarrier.arrive.release.cta.shared.b64 _, [%0];" :: "r"(a) : "memory")
#define MBAR_WAIT(a, ph) do { \
    asm volatile("{\n\t.reg .pred P;\n\tWL_%=:\n\t" \
        "mbarrier.try_wait.parity.acquire.cta.shared::cta.b64 P, [%0], %1, 0x989680;\n\t" \
        "@P bra.uni WD_%=;\n\tbra.uni WL_%=;\n\tWD_%=:\n\t}" \
        :: "r"(a), "r"(ph) : "memory"); } while (0)
#define FENCE_ASYNC() asm volatile("fence.proxy.async.shared::cta;" ::: "memory")

__device__ __forceinline__ void bulk_cp8k(uint32_t dst, const char* src, uint32_t mbar) {
    asm volatile(
        "cp.async.bulk.shared::cluster.global.mbarrier::complete_tx::bytes [%0], [%1], %2, [%3];"
        :: "r"(dst), "l"(src), "r"(8192u), "r"(mbar) : "memory");
}

// Fill slot with chunk: 4 x 8KB engine copies + expect_tx. ONE thread.
__device__ __forceinline__ void issue_fill(uint32_t sbase, uint32_t mbar,
                                           const char* ah, const char* al,
                                           const char* bh, const char* bl, int c) {
    const uint32_t dst = sbase + (uint32_t)(c % 3) * BUF_BYTES;
    const uint32_t off = (uint32_t)c * TILE_BYTES;
    MBAR_EXPECT(mbar, BUF_BYTES);
    bulk_cp8k(dst,                  ah + off, mbar);
    bulk_cp8k(dst + TILE_BYTES,     al + off, mbar);
    bulk_cp8k(dst + 2 * TILE_BYTES, bh + off, mbar);
    bulk_cp8k(dst + 3 * TILE_BYTES, bl + off, mbar);
}

// One K-chunk: acc += Ah*Bh + Ah*Bl + Al*Bh. All 12 LDSM4 up front, then a
// 48-MMA burst. DIAG path guards per-(mt,nt) with the warp-uniform keep mask.
template <bool DIAG>
__device__ __forceinline__ void compute_chunk(float acc[4][4][4], uint32_t bufu,
                                              int warp_m, int warp_n, int lane,
                                              uint32_t keep_mask) {
    const int arow = (lane & 7) + ((lane >> 3) & 1) * 8;
    const int aqad = lane >> 4;
    const int brow = (lane & 7) + ((lane >> 4) & 1) * 8;
    const int bqad = (lane >> 3) & 1;
    const uint32_t AH = bufu, AL = bufu + TILE_BYTES;
    const uint32_t BH = bufu + 2 * TILE_BYTES, BL = bufu + 3 * TILE_BYTES;

    #pragma unroll
    for (int ks = 0; ks < 2; ks++) {
        const int q0 = 2 * ks;
        uint32_t aH[4][4], aL[4][4], bH[4][2], bL[4][2];
        #pragma unroll
        for (int mt = 0; mt < 4; mt++) {
            if (DIAG && !((keep_mask >> (mt * 4)) & 0xF)) continue;
            int r = warp_m * 64 + mt * 16 + arow;
            LDSM4(aH[mt][0], aH[mt][1], aH[mt][2], aH[mt][3], AH + swz(r, q0 + aqad));
        }
        #pragma unroll
        for (int np = 0; np < 2; np++) {
            int r = warp_n * 32 + np * 16 + brow;
            LDSM4(bH[2 * np][0], bH[2 * np][1], bH[2 * np + 1][0], bH[2 * np + 1][1],
                  BH + swz(r, q0 + bqad));
        }
        #pragma unroll
        for (int np = 0; np < 2; np++) {
            int r = warp_n * 32 + np * 16 + brow;
            LDSM4(bL[2 * np][0], bL[2 * np][1], bL[2 * np + 1][0], bL[2 * np + 1][1],
                  BL + swz(r, q0 + bqad));
        }
        #pragma unroll
        for (int mt = 0; mt < 4; mt++) {
            if (DIAG && !((keep_mask >> (mt * 4)) & 0xF)) continue;
            int r = warp_m * 64 + mt * 16 + arow;
            LDSM4(aL[mt][0], aL[mt][1], aL[mt][2], aL[mt][3], AL + swz(r, q0 + aqad));
        }
        #pragma unroll
        for (int mt = 0; mt < 4; mt++)
            #pragma unroll
            for (int nt = 0; nt < 4; nt++)
                if (!DIAG || ((keep_mask >> (mt * 4 + nt)) & 1))
                    mma16816(acc[mt][nt], aH[mt], bH[nt]);
        #pragma unroll
        for (int mt = 0; mt < 4; mt++)
            #pragma unroll
            for (int nt = 0; nt < 4; nt++)
                if (!DIAG || ((keep_mask >> (mt * 4 + nt)) & 1))
                    mma16816(acc[mt][nt], aH[mt], bL[nt]);
        #pragma unroll
        for (int mt = 0; mt < 4; mt++)
            #pragma unroll
            for (int nt = 0; nt < 4; nt++)
                if (!DIAG || ((keep_mask >> (mt * 4 + nt)) & 1))
                    mma16816(acc[mt][nt], aL[mt], bH[nt]);
    }
}

// Producer/consumer mbarrier ring. Warps with keep_mask==0 traverse the ring
// IN ORDER (wait full, arrive empty) but skip compute (in-order arrivals avoid
// the R8/R9 phase-aliasing deadlock). Producer (tid 0) never has mask 0.
template <bool DIAG>
__device__ __forceinline__ void gemm_tile(float acc[4][4][4], char* smem,
                                          const uint64_t* full_sh, const uint64_t* empty_sh,
                                          const char* ah, const char* al,
                                          const char* bh, const char* bl,
                                          int warp_m, int warp_n, int lane, int tid,
                                          uint32_t keep_mask) {
    const uint32_t sbase = smem_u32(smem);
    uint32_t fb[3], eb[3];
    #pragma unroll
    for (int i = 0; i < 3; i++) { fb[i] = smem_u32(&full_sh[i]); eb[i] = smem_u32(&empty_sh[i]); }

    if (tid == 0) {
        issue_fill(sbase, fb[0], ah, al, bh, bl, 0);
        issue_fill(sbase, fb[1], ah, al, bh, bl, 1);
    }
    const bool wskip = DIAG && (keep_mask == 0);
    #pragma unroll 1
    for (int c = 0; c < 8; c++) {
        if (tid == 0 && c + 2 < 8) {
            const int gf = c + 2;
            if (gf >= 3) { MBAR_WAIT(eb[gf % 3], (gf / 3 - 1) & 1); FENCE_ASYNC(); }
            issue_fill(sbase, fb[gf % 3], ah, al, bh, bl, gf);
        }
        MBAR_WAIT(fb[c % 3], (c / 3) & 1);
        if (!wskip)
            compute_chunk<DIAG>(acc, sbase + (uint32_t)(c % 3) * BUF_BYTES,
                                warp_m, warp_n, lane, keep_mask);
        if (lane == 0) MBAR_ARRIVE(eb[c % 3]);
    }
}

// ---------------------------------------------------------------------------
// Prep: split X (MLP=4) and W^T into bf16 hi/lo planes, pre-swizzled layout.
// grid = 512 (X) + 64 (W) = 576.
// ---------------------------------------------------------------------------
__global__ __launch_bounds__(256) void prep_split(const float* __restrict__ X,
                                                  const float* __restrict__ Wu,
                                                  const float* __restrict__ Wl) {
    if (blockIdx.x < 512) {
        const int base = blockIdx.x * 256 + threadIdx.x;
        float4 v[4], v2[4];
        #pragma unroll
        for (int k = 0; k < 4; k++)
            v[k] = reinterpret_cast<const float4*>(X)[(base + k * 131072) * 2];
        #pragma unroll
        for (int k = 0; k < 4; k++)
            v2[k] = reinterpret_cast<const float4*>(X)[(base + k * 131072) * 2 + 1];
        #pragma unroll
        for (int k = 0; k < 4; k++) {
            const int idx = base + k * 131072;
            const int row = idx >> 5, cg = idx & 31;
            const int kc = cg >> 2, q = cg & 3;
            float f[8] = {v[k].x, v[k].y, v[k].z, v[k].w, v2[k].x, v2[k].y, v2[k].z, v2[k].w};
            uint32_t hw[4], lw[4];
            #pragma unroll
            for (int t = 0; t < 4; t++) {
                float a = f[2 * t], b = f[2 * t + 1];
                __nv_bfloat16 ah = __float2bfloat16(a), bh = __float2bfloat16(b);
                __nv_bfloat16 al = __float2bfloat16(a - __bfloat162float(ah));
                __nv_bfloat16 bl = __float2bfloat16(b - __bfloat162float(bh));
                hw[t] = bfu(ah) | (bfu(bh) << 16);
                lw[t] = bfu(al) | (bfu(bl) << 16);
            }
            size_t off = ((size_t)(row >> 7) * 8 + kc) * TILE_BYTES + swz(row & 127, q);
            *reinterpret_cast<uint4*>((char*)g_Xhi + off) = make_uint4(hw[0], hw[1], hw[2], hw[3]);
            *reinterpret_cast<uint4*>((char*)g_Xlo + off) = make_uint4(lw[0], lw[1], lw[2], lw[3]);
        }
    } else {
        int idx = (blockIdx.x - 512) * 256 + threadIdx.x;
        int w = idx >> 13, rem = idx & 8191;
        int n = rem >> 5, kg = rem & 31;
        int kc = kg >> 2, q = kg & 3;
        const float* src = (w ? Wl : Wu);
        uint32_t hw[4], lw[4];
        #pragma unroll
        for (int t = 0; t < 4; t++) {
            float a = src[(size_t)(kg * 8 + 2 * t) * 256 + n];
            float b = src[(size_t)(kg * 8 + 2 * t + 1) * 256 + n];
            __nv_bfloat16 ah = __float2bfloat16(a), bh = __float2bfloat16(b);
            __nv_bfloat16 al = __float2bfloat16(a - __bfloat162float(ah));
            __nv_bfloat16 bl = __float2bfloat16(b - __bfloat162float(bh));
            hw[t] = bfu(ah) | (bfu(bh) << 16);
            lw[t] = bfu(al) | (bfu(bl) << 16);
        }
        size_t off = ((size_t)(w * 2 + (n >> 7)) * 8 + kc) * TILE_BYTES + swz(n & 127, q);
        *reinterpret_cast<uint4*>((char*)g_Wthi + off) = make_uint4(hw[0], hw[1], hw[2], hw[3]);
        *reinterpret_cast<uint4*>((char*)g_Wtlo + off) = make_uint4(lw[0], lw[1], lw[2], lw[3]);
    }
}

// ---------------------------------------------------------------------------
// Stage 1: Y = X @ [Wu | Wl].  grid (128, 4). Epilogue writes swizzled Y.
// ---------------------------------------------------------------------------
__global__ __launch_bounds__(256, 2) void stage1_xw() {
    extern __shared__ char smem[];
    __shared__ __align__(8) uint64_t mb_full[3], mb_empty[3];
    const int tid = threadIdx.x, lane = tid & 31, wid = tid >> 5;
    const int warp_m = wid >> 2, warp_n = wid & 3;
    const int mb_ = blockIdx.x;               // 0..127
    const int ny = blockIdx.y;                // 0..3
    const int w = ny >> 1, nb = ny & 1;

    if (tid == 0) {
        #pragma unroll
        for (int k = 0; k < 3; k++) {
            MBAR_INIT(smem_u32(&mb_full[k]), 1);
            MBAR_INIT(smem_u32(&mb_empty[k]), 8);
        }
    }
    __syncthreads();

    const char* ah = (const char*)g_Xhi + (size_t)mb_ * BLOCK_BYTES;
    const char* al = (const char*)g_Xlo + (size_t)mb_ * BLOCK_BYTES;
    const char* bh = (const char*)g_Wthi + (size_t)(w * 2 + nb) * BLOCK_BYTES;
    const char* bl = (const char*)g_Wtlo + (size_t)(w * 2 + nb) * BLOCK_BYTES;

    float acc[4][4][4] = {};
    gemm_tile<false>(acc, smem, mb_full, mb_empty, ah, al, bh, bl,
                     warp_m, warp_n, lane, tid, 0xFFFFu);

    // Epilogue: split fp32 -> bf16 hi/lo, write into swizzled tiled Y layout.
    const int g = lane >> 2, c2 = (lane & 3) * 2;
    #pragma unroll
    for (int mt = 0; mt < 4; mt++) {
        #pragma unroll
        for (int nt = 0; nt < 4; nt++) {
            const int nl = nb * 128 + warp_n * 32 + nt * 8 + c2;
            const int kc = nl >> 5, q = (nl >> 3) & 3, e = nl & 7;
            #pragma unroll
            for (int h = 0; h < 2; h++) {
                const int r = warp_m * 64 + mt * 16 + g + 8 * h;
                float x = acc[mt][nt][2 * h];
                float y = acc[mt][nt][2 * h + 1];
                __nv_bfloat16 xh = __float2bfloat16(x), yh = __float2bfloat16(y);
                __nv_bfloat16 xl = __float2bfloat16(x - __bfloat162float(xh));
                __nv_bfloat16 yl = __float2bfloat16(y - __bfloat162float(yh));
                size_t off = ((size_t)(w * 128 + mb_) * 8 + kc) * TILE_BYTES
                           + swz(r, q) + e * 2;
                *(uint32_t*)((char*)g_Yhi + off) = bfu(xh) | (bfu(yh) << 16);
                *(uint32_t*)((char*)g_Ylo + off) = bfu(xl) | (bfu(yl) << 16);
            }
        }
    }
}

// ---------------------------------------------------------------------------
// Stage 2: adj[b,p,q] = dot(Ysel[b,p,:], X[b,q,:]) + bias_sel.
// grid (72, 16): 36 upper + 36 lower tile-passes; diagonal tiles split across
// two CTAs, with per-(mt,nt) triangle keep-masks inside diag CTAs.
// ---------------------------------------------------------------------------
__global__ __launch_bounds__(256, 2) void stage2_adj(const float* __restrict__ bu,
                                                     const float* __restrict__ bl,
                                                     float* __restrict__ out) {
    extern __shared__ char smem[];
    __shared__ __align__(8) uint64_t mb_full[3], mb_empty[3];
    const int tid = threadIdx.x, lane = tid & 31, wid = tid >> 5;
    const int warp_m = wid >> 2, warp_n = wid & 3;
    const int b = blockIdx.y;

    int t = blockIdx.x;                 // 0..71
    const int pass = (t >= 36) ? 1 : 0;
    int i = pass ? t - 36 : t;
    int r0 = 0;
    while (i >= 8 - r0) { i -= 8 - r0; r0++; }
    const int lo = r0, hi = r0 + i;     // lo <= hi
    const int pt = pass ? hi : lo;
    const int qt = pass ? lo : hi;
    const int p0 = pt * 128, q0 = qt * 128;
    const bool diag = (pt == qt);

    if (tid == 0) {
        #pragma unroll
        for (int k = 0; k < 3; k++) {
            MBAR_INIT(smem_u32(&mb_full[k]), 1);
            MBAR_INIT(smem_u32(&mb_empty[k]), 8);
        }
    }
    __syncthreads();

    const float bias = pass ? __ldg(bl) : __ldg(bu);
    const char* yh = (const char*)g_Yhi + (size_t)(pass * 128 + b * 8 + pt) * BLOCK_BYTES;
    const char* yl = (const char*)g_Ylo + (size_t)(pass * 128 + b * 8 + pt) * BLOCK_BYTES;
    const char* xh = (const char*)g_Xhi + (size_t)(b * 8 + qt) * BLOCK_BYTES;
    const char* xl = (const char*)g_Xlo + (size_t)(b * 8 + qt) * BLOCK_BYTES;

    float acc[4][4][4] = {};
    if (!diag) {
        gemm_tile<false>(acc, smem, mb_full, mb_empty, yh, yl, xh, xl,
                         warp_m, warp_n, lane, tid, 0xFFFFu);
    } else {
        // Warp-uniform per-(mt,nt) keep mask: does this 16x8 tile touch the
        // triangle? (upper: pmin <= qmax; lower: pmax > qmin)
        uint32_t kmask = 0;
        #pragma unroll
        for (int mt = 0; mt < 4; mt++)
            #pragma unroll
            for (int nt = 0; nt < 4; nt++) {
                const int pmin = warp_m * 64 + mt * 16;
                const int qmin = warp_n * 32 + nt * 8;
                const bool keep = (pass == 0) ? (pmin <= qmin + 7)
                                              : (pmin + 15 > qmin);
                if (keep) kmask |= 1u << (mt * 4 + nt);
            }
        gemm_tile<true>(acc, smem, mb_full, mb_empty, yh, yl, xh, xl,
                        warp_m, warp_n, lane, tid, kmask);
        if (kmask == 0) return;
    }

    const int g = lane >> 2, c2 = (lane & 3) * 2;
    #pragma unroll
    for (int mt = 0; mt < 4; mt++) {
        #pragma unroll
        for (int nt = 0; nt < 4; nt++) {
            const int q = q0 + warp_n * 32 + nt * 8 + c2;
            #pragma unroll
            for (int h = 0; h < 2; h++) {
                const int p = p0 + warp_m * 64 + mt * 16 + g + 8 * h;
                float* dst = out + ((size_t)b << 20) + ((size_t)p << 10) + q;
                float v0 = acc[mt][nt][2 * h] + bias;
                float v1 = acc[mt][nt][2 * h + 1] + bias;
                if (!diag) {
                    *(float2*)dst = make_float2(v0, v1);
                } else if (pass == 0) {
                    if (p <= q)     dst[0] = v0;
                    if (p <= q + 1) dst[1] = v1;
                } else {
                    if (p > q)      dst[0] = v0;
                    if (p > q + 1)  dst[1] = v1;
                }
            }
        }
    }
}

// ---------------------------------------------------------------------------
// kernel_launch
// ---------------------------------------------------------------------------
extern "C" void kernel_launch(void* const* d_in, const int* in_sizes, int n_in,
                              void* d_out, int out_size) {
    const float* feats = (const float*)d_in[0];
    const float* Wu    = (const float*)d_in[1];
    const float* bu    = (const float*)d_in[2];
    const float* Wl    = (const float*)d_in[3];
    const float* bl    = (const float*)d_in[4];
    float* out = (float*)d_out;

    cudaFuncSetAttribute(stage1_xw,  cudaFuncAttributeMaxDynamicSharedMemorySize, SMEM_TOTAL);
    cudaFuncSetAttribute(stage2_adj, cudaFuncAttributeMaxDynamicSharedMemorySize, SMEM_TOTAL);

    prep_split<<<576, 256>>>(feats, Wu, Wl);
    stage1_xw<<<dim3(128, 4), 256, SMEM_TOTAL>>>();
    stage2_adj<<<dim3(72, 16), 256, SMEM_TOTAL>>>(bu, bl, out);
}

// round 15
// speedup vs baseline: 1.1484x; 1.1484x over previous
#include <cuda_runtime.h>
#include <cuda_bf16.h>
#include <cstdint>

#define NPTS 1024
#define DIM  256

// ---------------------------------------------------------------------------
// Scratch (__device__ globals). All PRE-SWIZZLED 8KB tile-chunks:
// block = 128 rows x 32 cols(bf16), row r / quad q at offset swz(r,q).
// ---------------------------------------------------------------------------
__device__ __align__(16) __nv_bfloat16 g_Xhi[16384 * 256];
__device__ __align__(16) __nv_bfloat16 g_Xlo[16384 * 256];
__device__ __align__(16) __nv_bfloat16 g_Wthi[2 * 256 * 256];
__device__ __align__(16) __nv_bfloat16 g_Wtlo[2 * 256 * 256];
__device__ __align__(16) __nv_bfloat16 g_Yhi[2 * 16384 * 256];
__device__ __align__(16) __nv_bfloat16 g_Ylo[2 * 16384 * 256];

#define TILE_BYTES 8192
#define BLOCK_BYTES 65536
#define BUF_BYTES  (4 * TILE_BYTES)   // Ah, Al, Bh, Bl = 32768
#define SMEM_TOTAL (3 * BUF_BYTES)    // 98304; x2 CTAs = 192K <= 228K/SM

__device__ __forceinline__ uint32_t smem_u32(const void* p) {
    uint32_t a;
    asm("{ .reg .u64 t; cvta.to.shared.u64 t, %1; cvt.u32.u64 %0, t; }" : "=r"(a) : "l"(p));
    return a;
}
__device__ __forceinline__ uint32_t bfu(__nv_bfloat16 v) {
    return (uint32_t)__bfloat16_as_ushort(v);
}
__device__ __forceinline__ uint32_t swz(int r, int q) {
    return (uint32_t)(r * 64 + (((q + (r >> 1)) & 3) << 4));
}

__device__ __forceinline__ void mma16816(float* d, const uint32_t* a, const uint32_t* b) {
    asm volatile(
        "mma.sync.aligned.m16n8k16.row.col.f32.bf16.bf16.f32 "
        "{%0,%1,%2,%3}, {%4,%5,%6,%7}, {%8,%9}, {%0,%1,%2,%3};\n"
        : "+f"(d[0]), "+f"(d[1]), "+f"(d[2]), "+f"(d[3])
        : "r"(a[0]), "r"(a[1]), "r"(a[2]), "r"(a[3]), "r"(b[0]), "r"(b[1]));
}
#define LDSM4(r0, r1, r2, r3, addr) \
    asm volatile("ldmatrix.sync.aligned.m8n8.x4.shared.b16 {%0,%1,%2,%3}, [%4];" \
        : "=r"(r0), "=r"(r1), "=r"(r2), "=r"(r3) : "r"(addr))

#define MBAR_INIT(a, c) \
    asm volatile("mbarrier.init.shared.b64 [%0], %1;" :: "r"(a), "r"(c) : "memory")
#define MBAR_EXPECT(a, n) \
    asm volatile("mbarrier.arrive.expect_tx.shared.b64 _, [%0], %1;" :: "r"(a), "r"(n) : "memory")
#define MBAR_ARRIVE(a) \
    asm volatile("mbarrier.arrive.release.cta.shared.b64 _, [%0];" :: "r"(a) : "memory")
#define MBAR_WAIT(a, ph) do { \
    asm volatile("{\n\t.reg .pred P;\n\tWL_%=:\n\t" \
        "mbarrier.try_wait.parity.acquire.cta.shared::cta.b64 P, [%0], %1, 0x989680;\n\t" \
        "@P bra.uni WD_%=;\n\tbra.uni WL_%=;\n\tWD_%=:\n\t}" \
        :: "r"(a), "r"(ph) : "memory"); } while (0)
#define FENCE_ASYNC() asm volatile("fence.proxy.async.shared::cta;" ::: "memory")

__device__ __forceinline__ void bulk_cp8k(uint32_t dst, const char* src, uint32_t mbar) {
    asm volatile(
        "cp.async.bulk.shared::cluster.global.mbarrier::complete_tx::bytes [%0], [%1], %2, [%3];"
        :: "r"(dst), "l"(src), "r"(8192u), "r"(mbar) : "memory");
}

// Fill slot with chunk: 4 x 8KB engine copies + expect_tx. ONE thread.
__device__ __forceinline__ void issue_fill(uint32_t sbase, uint32_t mbar,
                                           const char* ah, const char* al,
                                           const char* bh, const char* bl, int c) {
    const uint32_t dst = sbase + (uint32_t)(c % 3) * BUF_BYTES;
    const uint32_t off = (uint32_t)c * TILE_BYTES;
    MBAR_EXPECT(mbar, BUF_BYTES);
    bulk_cp8k(dst,                  ah + off, mbar);
    bulk_cp8k(dst + TILE_BYTES,     al + off, mbar);
    bulk_cp8k(dst + 2 * TILE_BYTES, bh + off, mbar);
    bulk_cp8k(dst + 3 * TILE_BYTES, bl + off, mbar);
}

// One K-chunk: acc += Ah*Bh + Ah*Bl + Al*Bh. Per k-slice: ALL 12 LDSM4 up
// front (one dependency head), then an uninterrupted 48-MMA burst.
__device__ __forceinline__ void compute_chunk(float acc[4][4][4], uint32_t bufu,
                                              int warp_m, int warp_n, int lane) {
    const int arow = (lane & 7) + ((lane >> 3) & 1) * 8;
    const int aqad = lane >> 4;
    const int brow = (lane & 7) + ((lane >> 4) & 1) * 8;
    const int bqad = (lane >> 3) & 1;
    const uint32_t AH = bufu, AL = bufu + TILE_BYTES;
    const uint32_t BH = bufu + 2 * TILE_BYTES, BL = bufu + 3 * TILE_BYTES;

    #pragma unroll
    for (int ks = 0; ks < 2; ks++) {
        const int q0 = 2 * ks;
        uint32_t aH[4][4], aL[4][4], bH[4][2], bL[4][2];
        // ---- fragment load burst: 12 x LDSM4 ----
        #pragma unroll
        for (int mt = 0; mt < 4; mt++) {
            int r = warp_m * 64 + mt * 16 + arow;
            LDSM4(aH[mt][0], aH[mt][1], aH[mt][2], aH[mt][3], AH + swz(r, q0 + aqad));
        }
        #pragma unroll
        for (int np = 0; np < 2; np++) {
            int r = warp_n * 32 + np * 16 + brow;
            LDSM4(bH[2 * np][0], bH[2 * np][1], bH[2 * np + 1][0], bH[2 * np + 1][1],
                  BH + swz(r, q0 + bqad));
        }
        #pragma unroll
        for (int np = 0; np < 2; np++) {
            int r = warp_n * 32 + np * 16 + brow;
            LDSM4(bL[2 * np][0], bL[2 * np][1], bL[2 * np + 1][0], bL[2 * np + 1][1],
                  BL + swz(r, q0 + bqad));
        }
        #pragma unroll
        for (int mt = 0; mt < 4; mt++) {
            int r = warp_m * 64 + mt * 16 + arow;
            LDSM4(aL[mt][0], aL[mt][1], aL[mt][2], aL[mt][3], AL + swz(r, q0 + aqad));
        }
        // ---- MMA burst: 48 HMMA, 16 distinct accumulators per product ----
        #pragma unroll
        for (int mt = 0; mt < 4; mt++)
            #pragma unroll
            for (int nt = 0; nt < 4; nt++) mma16816(acc[mt][nt], aH[mt], bH[nt]);
        #pragma unroll
        for (int mt = 0; mt < 4; mt++)
            #pragma unroll
            for (int nt = 0; nt < 4; nt++) mma16816(acc[mt][nt], aH[mt], bL[nt]);
        #pragma unroll
        for (int mt = 0; mt < 4; mt++)
            #pragma unroll
            for (int nt = 0; nt < 4; nt++) mma16816(acc[mt][nt], aL[mt], bH[nt]);
    }
}

// Producer/consumer mbarrier ring. wskip warps traverse the ring IN ORDER
// (wait full, arrive empty) but skip the compute — in-order arrivals prevent
// the phase-aliasing deadlock (R8/R9). Producer (tid 0) never skips.
__device__ __forceinline__ void gemm_tile(float acc[4][4][4], char* smem,
                                          const uint64_t* full_sh, const uint64_t* empty_sh,
                                          const char* ah, const char* al,
                                          const char* bh, const char* bl,
                                          int warp_m, int warp_n, int lane, int tid,
                                          bool wskip) {
    const uint32_t sbase = smem_u32(smem);
    uint32_t fb[3], eb[3];
    #pragma unroll
    for (int i = 0; i < 3; i++) { fb[i] = smem_u32(&full_sh[i]); eb[i] = smem_u32(&empty_sh[i]); }

    if (tid == 0) {
        issue_fill(sbase, fb[0], ah, al, bh, bl, 0);
        issue_fill(sbase, fb[1], ah, al, bh, bl, 1);
    }
    #pragma unroll 1
    for (int c = 0; c < 8; c++) {
        if (tid == 0 && c + 2 < 8) {
            const int gf = c + 2;
            if (gf >= 3) { MBAR_WAIT(eb[gf % 3], (gf / 3 - 1) & 1); FENCE_ASYNC(); }
            issue_fill(sbase, fb[gf % 3], ah, al, bh, bl, gf);
        }
        MBAR_WAIT(fb[c % 3], (c / 3) & 1);
        if (!wskip)
            compute_chunk(acc, sbase + (uint32_t)(c % 3) * BUF_BYTES, warp_m, warp_n, lane);
        if (lane == 0) MBAR_ARRIVE(eb[c % 3]);
    }
}

// ---------------------------------------------------------------------------
// Prep: split X (MLP=4) and W^T into bf16 hi/lo planes, pre-swizzled layout.
// grid = 512 (X) + 64 (W) = 576.
// ---------------------------------------------------------------------------
__global__ __launch_bounds__(256) void prep_split(const float* __restrict__ X,
                                                  const float* __restrict__ Wu,
                                                  const float* __restrict__ Wl) {
    if (blockIdx.x < 512) {
        const int base = blockIdx.x * 256 + threadIdx.x;
        float4 v[4], v2[4];
        #pragma unroll
        for (int k = 0; k < 4; k++)
            v[k] = reinterpret_cast<const float4*>(X)[(base + k * 131072) * 2];
        #pragma unroll
        for (int k = 0; k < 4; k++)
            v2[k] = reinterpret_cast<const float4*>(X)[(base + k * 131072) * 2 + 1];
        #pragma unroll
        for (int k = 0; k < 4; k++) {
            const int idx = base + k * 131072;
            const int row = idx >> 5, cg = idx & 31;
            const int kc = cg >> 2, q = cg & 3;
            float f[8] = {v[k].x, v[k].y, v[k].z, v[k].w, v2[k].x, v2[k].y, v2[k].z, v2[k].w};
            uint32_t hw[4], lw[4];
            #pragma unroll
            for (int t = 0; t < 4; t++) {
                float a = f[2 * t], b = f[2 * t + 1];
                __nv_bfloat16 ah = __float2bfloat16(a), bh = __float2bfloat16(b);
                __nv_bfloat16 al = __float2bfloat16(a - __bfloat162float(ah));
                __nv_bfloat16 bl = __float2bfloat16(b - __bfloat162float(bh));
                hw[t] = bfu(ah) | (bfu(bh) << 16);
                lw[t] = bfu(al) | (bfu(bl) << 16);
            }
            size_t off = ((size_t)(row >> 7) * 8 + kc) * TILE_BYTES + swz(row & 127, q);
            *reinterpret_cast<uint4*>((char*)g_Xhi + off) = make_uint4(hw[0], hw[1], hw[2], hw[3]);
            *reinterpret_cast<uint4*>((char*)g_Xlo + off) = make_uint4(lw[0], lw[1], lw[2], lw[3]);
        }
    } else {
        int idx = (blockIdx.x - 512) * 256 + threadIdx.x;
        int w = idx >> 13, rem = idx & 8191;
        int n = rem >> 5, kg = rem & 31;
        int kc = kg >> 2, q = kg & 3;
        const float* src = (w ? Wl : Wu);
        uint32_t hw[4], lw[4];
        #pragma unroll
        for (int t = 0; t < 4; t++) {
            float a = src[(size_t)(kg * 8 + 2 * t) * 256 + n];
            float b = src[(size_t)(kg * 8 + 2 * t + 1) * 256 + n];
            __nv_bfloat16 ah = __float2bfloat16(a), bh = __float2bfloat16(b);
            __nv_bfloat16 al = __float2bfloat16(a - __bfloat162float(ah));
            __nv_bfloat16 bl = __float2bfloat16(b - __bfloat162float(bh));
            hw[t] = bfu(ah) | (bfu(bh) << 16);
            lw[t] = bfu(al) | (bfu(bl) << 16);
        }
        size_t off = ((size_t)(w * 2 + (n >> 7)) * 8 + kc) * TILE_BYTES + swz(n & 127, q);
        *reinterpret_cast<uint4*>((char*)g_Wthi + off) = make_uint4(hw[0], hw[1], hw[2], hw[3]);
        *reinterpret_cast<uint4*>((char*)g_Wtlo + off) = make_uint4(lw[0], lw[1], lw[2], lw[3]);
    }
}

// ---------------------------------------------------------------------------
// Stage 1: Y = X @ [Wu | Wl].  grid (128, 4). Epilogue writes swizzled Y.
// ---------------------------------------------------------------------------
__global__ __launch_bounds__(256, 2) void stage1_xw() {
    extern __shared__ char smem[];
    __shared__ __align__(8) uint64_t mb_full[3], mb_empty[3];
    const int tid = threadIdx.x, lane = tid & 31, wid = tid >> 5;
    const int warp_m = wid >> 2, warp_n = wid & 3;
    const int mb_ = blockIdx.x;               // 0..127
    const int ny = blockIdx.y;                // 0..3
    const int w = ny >> 1, nb = ny & 1;

    if (tid == 0) {
        #pragma unroll
        for (int k = 0; k < 3; k++) {
            MBAR_INIT(smem_u32(&mb_full[k]), 1);
            MBAR_INIT(smem_u32(&mb_empty[k]), 8);
        }
    }
    __syncthreads();

    const char* ah = (const char*)g_Xhi + (size_t)mb_ * BLOCK_BYTES;
    const char* al = (const char*)g_Xlo + (size_t)mb_ * BLOCK_BYTES;
    const char* bh = (const char*)g_Wthi + (size_t)(w * 2 + nb) * BLOCK_BYTES;
    const char* bl = (const char*)g_Wtlo + (size_t)(w * 2 + nb) * BLOCK_BYTES;

    float acc[4][4][4] = {};
    gemm_tile(acc, smem, mb_full, mb_empty, ah, al, bh, bl, warp_m, warp_n, lane, tid, false);

    // Epilogue: split fp32 -> bf16 hi/lo, write into swizzled tiled Y layout.
    const int g = lane >> 2, c2 = (lane & 3) * 2;
    #pragma unroll
    for (int mt = 0; mt < 4; mt++) {
        #pragma unroll
        for (int nt = 0; nt < 4; nt++) {
            const int nl = nb * 128 + warp_n * 32 + nt * 8 + c2;
            const int kc = nl >> 5, q = (nl >> 3) & 3, e = nl & 7;
            #pragma unroll
            for (int h = 0; h < 2; h++) {
                const int r = warp_m * 64 + mt * 16 + g + 8 * h;
                float x = acc[mt][nt][2 * h];
                float y = acc[mt][nt][2 * h + 1];
                __nv_bfloat16 xh = __float2bfloat16(x), yh = __float2bfloat16(y);
                __nv_bfloat16 xl = __float2bfloat16(x - __bfloat162float(xh));
                __nv_bfloat16 yl = __float2bfloat16(y - __bfloat162float(yh));
                size_t off = ((size_t)(w * 128 + mb_) * 8 + kc) * TILE_BYTES
                           + swz(r, q) + e * 2;
                *(uint32_t*)((char*)g_Yhi + off) = bfu(xh) | (bfu(yh) << 16);
                *(uint32_t*)((char*)g_Ylo + off) = bfu(xl) | (bfu(yl) << 16);
            }
        }
    }
}

// ---------------------------------------------------------------------------
// Stage 2: adj[b,p,q] = dot(Ysel[b,p,:], X[b,q,:]) + bias_sel.
// grid (72, 16): 36 upper + 36 lower tile-passes; diagonal tiles split across
// two CTAs, with whole-warp triangle skip inside diag CTAs.
// ---------------------------------------------------------------------------
__global__ __launch_bounds__(256, 2) void stage2_adj(const float* __restrict__ bu,
                                                     const float* __restrict__ bl,
                                                     float* __restrict__ out) {
    extern __shared__ char smem[];
    __shared__ __align__(8) uint64_t mb_full[3], mb_empty[3];
    const int tid = threadIdx.x, lane = tid & 31, wid = tid >> 5;
    const int warp_m = wid >> 2, warp_n = wid & 3;
    const int b = blockIdx.y;

    int t = blockIdx.x;                 // 0..71
    const int pass = (t >= 36) ? 1 : 0;
    int i = pass ? t - 36 : t;
    int r0 = 0;
    while (i >= 8 - r0) { i -= 8 - r0; r0++; }
    const int lo = r0, hi = r0 + i;     // lo <= hi
    const int pt = pass ? hi : lo;
    const int qt = pass ? lo : hi;
    const int p0 = pt * 128, q0 = qt * 128;
    const bool diag = (pt == qt);

    if (tid == 0) {
        #pragma unroll
        for (int k = 0; k < 3; k++) {
            MBAR_INIT(smem_u32(&mb_full[k]), 1);
            MBAR_INIT(smem_u32(&mb_empty[k]), 8);
        }
    }
    __syncthreads();

    const float bias = pass ? __ldg(bl) : __ldg(bu);
    const char* yh = (const char*)g_Yhi + (size_t)(pass * 128 + b * 8 + pt) * BLOCK_BYTES;
    const char* yl = (const char*)g_Ylo + (size_t)(pass * 128 + b * 8 + pt) * BLOCK_BYTES;
    const char* xh = (const char*)g_Xhi + (size_t)(b * 8 + qt) * BLOCK_BYTES;
    const char* xl = (const char*)g_Xlo + (size_t)(b * 8 + qt) * BLOCK_BYTES;

    // Whole-warp triangle skip on diagonal tiles (never warp 0 = producer).
    const bool wskip = diag && (pass == 0 ? (2 * warp_m >= warp_n + 1)
                                          : (64 * warp_m + 64 <= 32 * warp_n));

    float acc[4][4][4] = {};
    gemm_tile(acc, smem, mb_full, mb_empty, yh, yl, xh, xl, warp_m, warp_n, lane, tid, wskip);
    if (wskip) return;

    const int g = lane >> 2, c2 = (lane & 3) * 2;
    #pragma unroll
    for (int mt = 0; mt < 4; mt++) {
        #pragma unroll
        for (int nt = 0; nt < 4; nt++) {
            const int q = q0 + warp_n * 32 + nt * 8 + c2;
            #pragma unroll
            for (int h = 0; h < 2; h++) {
                const int p = p0 + warp_m * 64 + mt * 16 + g + 8 * h;
                float* dst = out + ((size_t)b << 20) + ((size_t)p << 10) + q;
                float v0 = acc[mt][nt][2 * h] + bias;
                float v1 = acc[mt][nt][2 * h + 1] + bias;
                if (!diag) {
                    *(float2*)dst = make_float2(v0, v1);
                } else if (pass == 0) {
                    if (p <= q)     dst[0] = v0;
                    if (p <= q + 1) dst[1] = v1;
                } else {
                    if (p > q)      dst[0] = v0;
                    if (p > q + 1)  dst[1] = v1;
                }
            }
        }
    }
}

// ---------------------------------------------------------------------------
// kernel_launch
// ---------------------------------------------------------------------------
extern "C" void kernel_launch(void* const* d_in, const int* in_sizes, int n_in,
                              void* d_out, int out_size) {
    const float* feats = (const float*)d_in[0];
    const float* Wu    = (const float*)d_in[1];
    const float* bu    = (const float*)d_in[2];
    const float* Wl    = (const float*)d_in[3];
    const float* bl    = (const float*)d_in[4];
    float* out = (float*)d_out;

    cudaFuncSetAttribute(stage1_xw,  cudaFuncAttributeMaxDynamicSharedMemorySize, SMEM_TOTAL);
    cudaFuncSetAttribute(stage2_adj, cudaFuncAttributeMaxDynamicSharedMemorySize, SMEM_TOTAL);

    prep_split<<<576, 256>>>(feats, Wu, Wl);
    stage1_xw<<<dim3(128, 4), 256, SMEM_TOTAL>>>();
    stage2_adj<<<dim3(72, 16), 256, SMEM_TOTAL>>>(bu, bl, out);
}

// round 16
// speedup vs baseline: 2.2402x; 1.9507x over previous
#include <cuda_runtime.h>
#include <cuda_fp16.h>
#include <cstdint>

#define NPTS 1024
#define DIM  256

// ---------------------------------------------------------------------------
// Scratch: single fp16 planes, PRE-SWIZZLED 16KB tile-chunks.
// chunk = 128 rows x 64 k (fp16) = 16KB; 128B rows; quad q in 0..7 (16B units)
// at offset swz128(r, q). Block = 4 chunks (k=256) = 64KB.
//   g_Xf: [128 rowblocks][4 chunks][16384B]   (8 MB)
//   g_Wf: [2 w][2 nblocks][4 chunks][16384B]  (256 KB, n-major)
//   g_Yf: [2 w][128 rowblocks][4][16384B]     (16 MB)
// ---------------------------------------------------------------------------
__device__ __align__(16) __half g_Xf[16384 * 256];
__device__ __align__(16) __half g_Wf[2 * 256 * 256];
__device__ __align__(16) __half g_Yf[2 * 16384 * 256];

#define TILE_BYTES 16384
#define BLOCK_BYTES 65536             // 4 chunks per 128-row block
#define BUF_BYTES  (2 * TILE_BYTES)   // A, B = 32768
#define NCHUNKS 4
#define SMEM_TOTAL (3 * BUF_BYTES)    // 98304; x2 CTAs = 192K <= 228K/SM

__device__ __forceinline__ uint32_t smem_u32(const void* p) {
    uint32_t a;
    asm("{ .reg .u64 t; cvta.to.shared.u64 t, %1; cvt.u32.u64 %0, t; }" : "=r"(a) : "l"(p));
    return a;
}
// 128B-row swizzle: q' = (q + r) & 7 -> any 8 consecutive rows at fixed q
// cover all 8 16B-columns (conflict-free ldmatrix phases).
__device__ __forceinline__ uint32_t swz128(int r, int q) {
    return (uint32_t)(r * 128 + (((q + r) & 7) << 4));
}
__device__ __forceinline__ uint32_t h2u(__half a, __half b) {
    return (uint32_t)__half_as_ushort(a) | ((uint32_t)__half_as_ushort(b) << 16);
}

// HMMA fp16: D += A(16x16 f16, row) * B(16x8 f16, col), fp32 acc.
__device__ __forceinline__ void mma16816(float* d, const uint32_t* a, const uint32_t* b) {
    asm volatile(
        "mma.sync.aligned.m16n8k16.row.col.f32.f16.f16.f32 "
        "{%0,%1,%2,%3}, {%4,%5,%6,%7}, {%8,%9}, {%0,%1,%2,%3};\n"
        : "+f"(d[0]), "+f"(d[1]), "+f"(d[2]), "+f"(d[3])
        : "r"(a[0]), "r"(a[1]), "r"(a[2]), "r"(a[3]), "r"(b[0]), "r"(b[1]));
}
#define LDSM4(r0, r1, r2, r3, addr) \
    asm volatile("ldmatrix.sync.aligned.m8n8.x4.shared.b16 {%0,%1,%2,%3}, [%4];" \
        : "=r"(r0), "=r"(r1), "=r"(r2), "=r"(r3) : "r"(addr))

#define MBAR_INIT(a, c) \
    asm volatile("mbarrier.init.shared.b64 [%0], %1;" :: "r"(a), "r"(c) : "memory")
#define MBAR_EXPECT(a, n) \
    asm volatile("mbarrier.arrive.expect_tx.shared.b64 _, [%0], %1;" :: "r"(a), "r"(n) : "memory")
#define MBAR_ARRIVE(a) \
    asm volatile("mbarrier.arrive.release.cta.shared.b64 _, [%0];" :: "r"(a) : "memory")
#define MBAR_WAIT(a, ph) do { \
    asm volatile("{\n\t.reg .pred P;\n\tWL_%=:\n\t" \
        "mbarrier.try_wait.parity.acquire.cta.shared::cta.b64 P, [%0], %1, 0x989680;\n\t" \
        "@P bra.uni WD_%=;\n\tbra.uni WL_%=;\n\tWD_%=:\n\t}" \
        :: "r"(a), "r"(ph) : "memory"); } while (0)
#define FENCE_ASYNC() asm volatile("fence.proxy.async.shared::cta;" ::: "memory")

__device__ __forceinline__ void bulk_cp16k(uint32_t dst, const char* src, uint32_t mbar) {
    asm volatile(
        "cp.async.bulk.shared::cluster.global.mbarrier::complete_tx::bytes [%0], [%1], %2, [%3];"
        :: "r"(dst), "l"(src), "r"(16384u), "r"(mbar) : "memory");
}

// Fill slot with chunk c: A + B 16KB engine copies + expect_tx. ONE thread.
__device__ __forceinline__ void issue_fill(uint32_t sbase, uint32_t mbar,
                                           const char* a, const char* b, int c) {
    const uint32_t dst = sbase + (uint32_t)(c % 3) * BUF_BYTES;
    const uint32_t off = (uint32_t)c * TILE_BYTES;
    MBAR_EXPECT(mbar, BUF_BYTES);
    bulk_cp16k(dst,              a + off, mbar);
    bulk_cp16k(dst + TILE_BYTES, b + off, mbar);
}

// One K-chunk (k=64): 4 ksteps of k16; per kstep 6 LDSM4 + 16 MMA.
__device__ __forceinline__ void compute_chunk(float acc[4][4][4], uint32_t bufu,
                                              int warp_m, int warp_n, int lane) {
    const int arow = (lane & 7) + ((lane >> 3) & 1) * 8;
    const int aqad = lane >> 4;
    const int brow = (lane & 7) + ((lane >> 4) & 1) * 8;
    const int bqad = (lane >> 3) & 1;
    const uint32_t AT = bufu, BT = bufu + TILE_BYTES;

    #pragma unroll
    for (int ks = 0; ks < 4; ks++) {
        const int q0 = ks * 2;
        uint32_t aF[4][4], bF[4][2];
        #pragma unroll
        for (int mt = 0; mt < 4; mt++) {
            int r = warp_m * 64 + mt * 16 + arow;
            LDSM4(aF[mt][0], aF[mt][1], aF[mt][2], aF[mt][3], AT + swz128(r, q0 + aqad));
        }
        #pragma unroll
        for (int np = 0; np < 2; np++) {
            int r = warp_n * 32 + np * 16 + brow;
            LDSM4(bF[2 * np][0], bF[2 * np][1], bF[2 * np + 1][0], bF[2 * np + 1][1],
                  BT + swz128(r, q0 + bqad));
        }
        #pragma unroll
        for (int mt = 0; mt < 4; mt++)
            #pragma unroll
            for (int nt = 0; nt < 4; nt++) mma16816(acc[mt][nt], aF[mt], bF[nt]);
    }
}

// Producer/consumer mbarrier ring (3 stages, 4 chunks). wskip warps traverse
// the ring IN ORDER but skip compute (avoids R8/R9 phase-aliasing deadlock).
__device__ __forceinline__ void gemm_tile(float acc[4][4][4], char* smem,
                                          const uint64_t* full_sh, const uint64_t* empty_sh,
                                          const char* a, const char* b,
                                          int warp_m, int warp_n, int lane, int tid,
                                          bool wskip) {
    const uint32_t sbase = smem_u32(smem);
    uint32_t fb[3], eb[3];
    #pragma unroll
    for (int i = 0; i < 3; i++) { fb[i] = smem_u32(&full_sh[i]); eb[i] = smem_u32(&empty_sh[i]); }

    if (tid == 0) {
        issue_fill(sbase, fb[0], a, b, 0);
        issue_fill(sbase, fb[1], a, b, 1);
    }
    #pragma unroll 1
    for (int c = 0; c < NCHUNKS; c++) {
        if (tid == 0 && c + 2 < NCHUNKS) {
            const int gf = c + 2;
            if (gf >= 3) { MBAR_WAIT(eb[gf % 3], (gf / 3 - 1) & 1); FENCE_ASYNC(); }
            issue_fill(sbase, fb[gf % 3], a, b, gf);
        }
        MBAR_WAIT(fb[c % 3], (c / 3) & 1);
        if (!wskip)
            compute_chunk(acc, sbase + (uint32_t)(c % 3) * BUF_BYTES, warp_m, warp_n, lane);
        if (lane == 0) MBAR_ARRIVE(eb[c % 3]);
    }
}

// ---------------------------------------------------------------------------
// Prep: convert X (MLP=4) and W^T to fp16, pre-swizzled layout.
// grid = 512 (X) + 64 (W) = 576.
// ---------------------------------------------------------------------------
__global__ __launch_bounds__(256) void prep_split(const float* __restrict__ X,
                                                  const float* __restrict__ Wu,
                                                  const float* __restrict__ Wl) {
    if (blockIdx.x < 512) {
        const int base = blockIdx.x * 256 + threadIdx.x;   // 524288 groups of 8
        float4 v[4], v2[4];
        #pragma unroll
        for (int k = 0; k < 4; k++)
            v[k] = reinterpret_cast<const float4*>(X)[(base + k * 131072) * 2];
        #pragma unroll
        for (int k = 0; k < 4; k++)
            v2[k] = reinterpret_cast<const float4*>(X)[(base + k * 131072) * 2 + 1];
        #pragma unroll
        for (int k = 0; k < 4; k++) {
            const int idx = base + k * 131072;
            const int row = idx >> 5, g5 = idx & 31;       // 32 groups per 256-col row
            const int kc = g5 >> 3, q = g5 & 7;
            float f[8] = {v[k].x, v[k].y, v[k].z, v[k].w, v2[k].x, v2[k].y, v2[k].z, v2[k].w};
            uint32_t w0 = h2u(__float2half_rn(f[0]), __float2half_rn(f[1]));
            uint32_t w1 = h2u(__float2half_rn(f[2]), __float2half_rn(f[3]));
            uint32_t w2 = h2u(__float2half_rn(f[4]), __float2half_rn(f[5]));
            uint32_t w3 = h2u(__float2half_rn(f[6]), __float2half_rn(f[7]));
            size_t off = ((size_t)(row >> 7) * 4 + kc) * TILE_BYTES + swz128(row & 127, q);
            *reinterpret_cast<uint4*>((char*)g_Xf + off) = make_uint4(w0, w1, w2, w3);
        }
    } else {
        int idx = (blockIdx.x - 512) * 256 + threadIdx.x;  // 16384 groups: (w, n, g5)
        int w = idx >> 13, rem = idx & 8191;
        int n = rem >> 5, g5 = rem & 31;
        int kc = g5 >> 3, q = g5 & 7;
        const float* src = (w ? Wl : Wu);
        __half h[8];
        #pragma unroll
        for (int t = 0; t < 8; t++)
            h[t] = __float2half_rn(src[(size_t)(g5 * 8 + t) * 256 + n]);
        size_t off = ((size_t)(w * 2 + (n >> 7)) * 4 + kc) * TILE_BYTES + swz128(n & 127, q);
        *reinterpret_cast<uint4*>((char*)g_Wf + off) =
            make_uint4(h2u(h[0], h[1]), h2u(h[2], h[3]), h2u(h[4], h[5]), h2u(h[6], h[7]));
    }
}

// ---------------------------------------------------------------------------
// Stage 1: Y = X @ [Wu | Wl].  grid (128, 4). Epilogue writes swizzled fp16 Y.
// ---------------------------------------------------------------------------
__global__ __launch_bounds__(256, 2) void stage1_xw() {
    extern __shared__ char smem[];
    __shared__ __align__(8) uint64_t mb_full[3], mb_empty[3];
    const int tid = threadIdx.x, lane = tid & 31, wid = tid >> 5;
    const int warp_m = wid >> 2, warp_n = wid & 3;
    const int mb_ = blockIdx.x;               // 0..127
    const int ny = blockIdx.y;                // 0..3
    const int w = ny >> 1, nb = ny & 1;

    if (tid == 0) {
        #pragma unroll
        for (int k = 0; k < 3; k++) {
            MBAR_INIT(smem_u32(&mb_full[k]), 1);
            MBAR_INIT(smem_u32(&mb_empty[k]), 8);
        }
    }
    __syncthreads();

    const char* a = (const char*)g_Xf + (size_t)mb_ * BLOCK_BYTES;
    const char* b = (const char*)g_Wf + (size_t)(w * 2 + nb) * BLOCK_BYTES;

    float acc[4][4][4] = {};
    gemm_tile(acc, smem, mb_full, mb_empty, a, b, warp_m, warp_n, lane, tid, false);

    // Epilogue: round fp32 -> fp16, write into swizzled tiled Y layout.
    const int g = lane >> 2, c2 = (lane & 3) * 2;
    #pragma unroll
    for (int mt = 0; mt < 4; mt++) {
        #pragma unroll
        for (int nt = 0; nt < 4; nt++) {
            const int nl = nb * 128 + warp_n * 32 + nt * 8 + c2;   // 0..255 within w
            const int kc = nl >> 6, q = (nl >> 3) & 7, e = nl & 7; // e == c2 (4B aligned)
            #pragma unroll
            for (int h = 0; h < 2; h++) {
                const int r = warp_m * 64 + mt * 16 + g + 8 * h;
                uint32_t pk = h2u(__float2half_rn(acc[mt][nt][2 * h]),
                                  __float2half_rn(acc[mt][nt][2 * h + 1]));
                size_t off = ((size_t)(w * 128 + mb_) * 4 + kc) * TILE_BYTES
                           + swz128(r, q) + e * 2;
                *(uint32_t*)((char*)g_Yf + off) = pk;
            }
        }
    }
}

// ---------------------------------------------------------------------------
// Stage 2: adj[b,p,q] = dot(Ysel[b,p,:], X[b,q,:]) + bias_sel.
// grid (72, 16): 36 upper + 36 lower tile-passes; diagonal tiles split across
// two CTAs, with whole-warp triangle skip inside diag CTAs.
// ---------------------------------------------------------------------------
__global__ __launch_bounds__(256, 2) void stage2_adj(const float* __restrict__ bu,
                                                     const float* __restrict__ bl,
                                                     float* __restrict__ out) {
    extern __shared__ char smem[];
    __shared__ __align__(8) uint64_t mb_full[3], mb_empty[3];
    const int tid = threadIdx.x, lane = tid & 31, wid = tid >> 5;
    const int warp_m = wid >> 2, warp_n = wid & 3;
    const int b = blockIdx.y;

    int t = blockIdx.x;                 // 0..71
    const int pass = (t >= 36) ? 1 : 0;
    int i = pass ? t - 36 : t;
    int r0 = 0;
    while (i >= 8 - r0) { i -= 8 - r0; r0++; }
    const int lo = r0, hi = r0 + i;     // lo <= hi
    const int pt = pass ? hi : lo;
    const int qt = pass ? lo : hi;
    const int p0 = pt * 128, q0 = qt * 128;
    const bool diag = (pt == qt);

    if (tid == 0) {
        #pragma unroll
        for (int k = 0; k < 3; k++) {
            MBAR_INIT(smem_u32(&mb_full[k]), 1);
            MBAR_INIT(smem_u32(&mb_empty[k]), 8);
        }
    }
    __syncthreads();

    const float bias = pass ? __ldg(bl) : __ldg(bu);
    const char* a = (const char*)g_Yf + (size_t)(pass * 128 + b * 8 + pt) * BLOCK_BYTES;
    const char* bb = (const char*)g_Xf + (size_t)(b * 8 + qt) * BLOCK_BYTES;

    // Whole-warp triangle skip on diagonal tiles (never warp 0 = producer).
    const bool wskip = diag && (pass == 0 ? (2 * warp_m >= warp_n + 1)
                                          : (64 * warp_m + 64 <= 32 * warp_n));

    float acc[4][4][4] = {};
    gemm_tile(acc, smem, mb_full, mb_empty, a, bb, warp_m, warp_n, lane, tid, wskip);
    if (wskip) return;

    const int g = lane >> 2, c2 = (lane & 3) * 2;
    #pragma unroll
    for (int mt = 0; mt < 4; mt++) {
        #pragma unroll
        for (int nt = 0; nt < 4; nt++) {
            const int q = q0 + warp_n * 32 + nt * 8 + c2;
            #pragma unroll
            for (int h = 0; h < 2; h++) {
                const int p = p0 + warp_m * 64 + mt * 16 + g + 8 * h;
                float* dst = out + ((size_t)b << 20) + ((size_t)p << 10) + q;
                float v0 = acc[mt][nt][2 * h] + bias;
                float v1 = acc[mt][nt][2 * h + 1] + bias;
                if (!diag) {
                    *(float2*)dst = make_float2(v0, v1);
                } else if (pass == 0) {
                    if (p <= q)     dst[0] = v0;
                    if (p <= q + 1) dst[1] = v1;
                } else {
                    if (p > q)      dst[0] = v0;
                    if (p > q + 1)  dst[1] = v1;
                }
            }
        }
    }
}

// ---------------------------------------------------------------------------
// kernel_launch
// ---------------------------------------------------------------------------
extern "C" void kernel_launch(void* const* d_in, const int* in_sizes, int n_in,
                              void* d_out, int out_size) {
    const float* feats = (const float*)d_in[0];
    const float* Wu    = (const float*)d_in[1];
    const float* bu    = (const float*)d_in[2];
    const float* Wl    = (const float*)d_in[3];
    const float* bl    = (const float*)d_in[4];
    float* out = (float*)d_out;

    cudaFuncSetAttribute(stage1_xw,  cudaFuncAttributeMaxDynamicSharedMemorySize, SMEM_TOTAL);
    cudaFuncSetAttribute(stage2_adj, cudaFuncAttributeMaxDynamicSharedMemorySize, SMEM_TOTAL);

    prep_split<<<576, 256>>>(feats, Wu, Wl);
    stage1_xw<<<dim3(128, 4), 256, SMEM_TOTAL>>>();
    stage2_adj<<<dim3(72, 16), 256, SMEM_TOTAL>>>(bu, bl, out);
}